// round 15
// baseline (speedup 1.0000x reference)
#include <cuda_runtime.h>
#include <math.h>
#include <cstdint>

// ---------------- problem constants ----------------
#define MTOT 16384
#define KDIM 4096
#define EEXP 64
#define NCMB 128
#define TOPK 8
#define WOFF 0
#define IOFF (MTOT * TOPK)
#define POFF (2 * MTOT * TOPK)

#define GAPTHRESH 2.0e-4f

// ---------------- GEMM config ----------------
#define BM 128
#define BK 32
#define KITER (KDIM / BK)        // 128
#define NSTAGE 3
#define A_ROW_B 160              // A smem row stride bytes (40 floats, 16B mult)
#define A_TILE_B (BM * A_ROW_B)          // 20480
#define B_TILE_B (16 * 1024)             // 16 k-pairs x 128 float2 = 16384
#define STAGE_B (A_TILE_B + B_TILE_B)    // 36864
#define SMEM_B (NSTAGE * STAGE_B)        // 110592  (also covers 67584B logits tile)
#define LSTRIDE 132                      // logits smem row stride (floats)

typedef unsigned long long ull;

// scratch
__device__ float2 g_Bint[(KDIM / 2) * NCMB];   // [kpair][n] = {W[2kp][n], W[2kp+1][n]}
__device__ int    g_nflag;
__device__ int    g_flagged[MTOT];

// ---------------- helpers ----------------
__device__ __forceinline__ uint32_t smem_u32(const void* p) {
    uint32_t a;
    asm("{ .reg .u64 t; cvta.to.shared.u64 t, %1; cvt.u32.u64 %0, t; }" : "=r"(a) : "l"(p));
    return a;
}
#define CP16(dst, src) asm volatile("cp.async.cg.shared.global [%0], [%1], 16;" :: "r"(dst), "l"(src) : "memory")
#define CP_COMMIT()    asm volatile("cp.async.commit_group;" ::: "memory")
#define CP_WAIT1()     asm volatile("cp.async.wait_group 1;" ::: "memory")
#define CP_WAIT0()     asm volatile("cp.async.wait_group 0;" ::: "memory")

// packed fp32x2 FMA: d.lo += a.lo*b.lo ; d.hi += a.hi*b.hi   (exact fp32 lanes)
#define FMA_F32X2(d, a, b) \
    asm("fma.rn.f32x2 %0, %1, %2, %0;" : "+l"(d) : "l"(a), "l"(b))

__device__ __forceinline__ float f32x2_sum(ull v) {
    float2 f = *reinterpret_cast<float2*>(&v);
    return f.x + f.y;
}

__device__ __forceinline__ float softplus_f(float z) {
    return fmaxf(z, 0.0f) + log1pf(expf(-fabsf(z)));
}

// ---------------------------------------------------------------------------
__global__ void reset_flags() { if (threadIdx.x == 0) g_nflag = 0; }

// ---------------------------------------------------------------------------
// Prep: interleave W into k-pair-major float2 tiles: g_Bint[kp][n]
//   n in [0,64): W_route ; n in [64,128): W_noise
// ---------------------------------------------------------------------------
__global__ void prep_interleave(const float* __restrict__ Wr, const float* __restrict__ Wn) {
    const int g = blockIdx.x * blockDim.x + threadIdx.x;   // 0 .. 2048*128-1
    const int kp = g >> 7;
    const int n  = g & 127;
    const int k0 = kp * 2;
    float x0, x1;
    if (n < EEXP) {
        x0 = Wr[(size_t)k0 * EEXP + n];
        x1 = Wr[(size_t)(k0 + 1) * EEXP + n];
    } else {
        x0 = Wn[(size_t)k0 * EEXP + (n - EEXP)];
        x1 = Wn[(size_t)(k0 + 1) * EEXP + (n - EEXP)];
    }
    g_Bint[g] = make_float2(x0, x1);
}

// ---------------------------------------------------------------------------
// Fused GEMM (packed f32x2, exact fp32) + router + flagging.
// CTA: 128 tokens x 128 experts, 256 threads (ty=tid>>4 m-sub, tx=tid&15 n-sub)
// thread tile: 8m x 8n, n columns = tx + 16*j (conflict-free b loads)
// acc2 lanes: lo = even-k partial sum, hi = odd-k partial sum
// ---------------------------------------------------------------------------
__global__ __launch_bounds__(256, 1)
void gemm_fused(const float* __restrict__ X,
                const float* __restrict__ noise,
                const float* __restrict__ b_route,
                const float* __restrict__ b_noise,
                float* __restrict__ out)
{
    extern __shared__ char smem[];
    const uint32_t sb = smem_u32(smem);
    const int tid = threadIdx.x;
    const int ty = tid >> 4, tx = tid & 15;
    const int m0 = blockIdx.x * BM;

    // ---- cp.async mappings ----
    const int arow = tid >> 1, ahalf = tid & 1;
    const float* aSrc = X + (size_t)(m0 + arow) * KDIM + ahalf * 16;
    const uint32_t aDst = sb + arow * A_ROW_B + ahalf * 64;
    const int brow = tid >> 4, bcol = (tid & 15) * 64;
    const char* bSrc = reinterpret_cast<const char*>(g_Bint) + (size_t)brow * 1024 + bcol;
    const uint32_t bDst = sb + A_TILE_B + brow * 1024 + bcol;

    auto issue_stage = [&](int kt) {
        const uint32_t so = (kt % NSTAGE) * STAGE_B;
        const float* as = aSrc + kt * BK;
#pragma unroll
        for (int j = 0; j < 4; j++) CP16(so + aDst + j * 16, as + j * 4);
        const char* bs = bSrc + (size_t)kt * (16 * 1024);
#pragma unroll
        for (int j = 0; j < 4; j++) CP16(so + bDst + j * 16, bs + j * 16);
        CP_COMMIT();
    };

    issue_stage(0);
    issue_stage(1);

    ull acc[8][8];
#pragma unroll
    for (int i = 0; i < 8; i++)
#pragma unroll
        for (int j = 0; j < 8; j++) acc[i][j] = 0ull;

    for (int it = 0; it < KITER; ++it) {
        if (it == KITER - 1) { CP_WAIT0(); } else { CP_WAIT1(); }
        __syncthreads();

        if (it + 2 < KITER) issue_stage(it + 2);

        const char* base = smem + (it % NSTAGE) * STAGE_B;
        const char* aB = base + ty * (8 * A_ROW_B);
        const char* bB = base + A_TILE_B + tx * 8;

#pragma unroll 4
        for (int kp = 0; kp < 16; kp++) {
            ull a8[8], b8[8];
#pragma unroll
            for (int ii = 0; ii < 8; ii++)
                a8[ii] = *reinterpret_cast<const ull*>(aB + ii * A_ROW_B + kp * 8);
#pragma unroll
            for (int jj = 0; jj < 8; jj++)
                b8[jj] = *reinterpret_cast<const ull*>(bB + kp * 1024 + jj * 128);
#pragma unroll
            for (int ii = 0; ii < 8; ii++)
#pragma unroll
                for (int jj = 0; jj < 8; jj++)
                    FMA_F32X2(acc[ii][jj], a8[ii], b8[jj]);
        }
    }

    // ---- epilogue: logits tile to smem ----
    __syncthreads();
    float* slog = reinterpret_cast<float*>(smem);
#pragma unroll
    for (int ii = 0; ii < 8; ii++)
#pragma unroll
        for (int jj = 0; jj < 8; jj++)
            slog[(ty * 8 + ii) * LSTRIDE + (tx + 16 * jj)] = f32x2_sum(acc[ii][jj]);
    __syncthreads();

    // ---- fused router: warp w handles tokens w*16 .. w*16+15 ----
    const int wid = tid >> 5, lane = tid & 31;
    const int e0 = lane, e1 = lane + 32;
    const float br0 = b_route[e0], br1 = b_route[e1];
    const float bn0 = b_noise[e0], bn1 = b_noise[e1];

    for (int t = 0; t < 16; t++) {
        const int tl = wid * 16 + t;
        const int token = m0 + tl;
        const float* lr = slog + tl * LSTRIDE;

        const float* nz = noise + (size_t)token * EEXP;
        float l0 = (lr[e0] + br0) + nz[e0] * softplus_f(lr[EEXP + e0] + bn0);
        float l1 = (lr[e1] + br1) + nz[e1] * softplus_f(lr[EEXP + e1] + bn1);

        float mx = fmaxf(l0, l1);
#pragma unroll
        for (int o = 16; o > 0; o >>= 1) mx = fmaxf(mx, __shfl_xor_sync(0xFFFFFFFFu, mx, o));
        float p0 = expf(l0 - mx);
        float p1 = expf(l1 - mx);
        float sum = p0 + p1;
#pragma unroll
        for (int o = 16; o > 0; o >>= 1) sum += __shfl_xor_sync(0xFFFFFFFFu, sum, o);
        p0 /= sum;
        p1 /= sum;

        out[POFF + (size_t)token * EEXP + e0] = p0;
        out[POFF + (size_t)token * EEXP + e1] = p1;

        float v0 = p0, v1 = p1;
        float myv = 0.0f;
        int   mye = 0;
        float tsum = 0.0f;

#pragma unroll
        for (int i = 0; i < TOPK; i++) {
            float cv; int ce;
            if (v1 > v0) { cv = v1; ce = e1; } else { cv = v0; ce = e0; }
#pragma unroll
            for (int o = 16; o > 0; o >>= 1) {
                float ov = __shfl_xor_sync(0xFFFFFFFFu, cv, o);
                int   oe = __shfl_xor_sync(0xFFFFFFFFu, ce, o);
                if (ov > cv || (ov == cv && oe < ce)) { cv = ov; ce = oe; }
            }
            tsum += cv;
            if (lane == i) { myv = cv; mye = ce; }
            if (ce == e0) v0 = -1e30f;
            else if (ce == e1) v1 = -1e30f;
        }

        if (lane < TOPK) {
            out[WOFF + (size_t)token * TOPK + lane] = myv / tsum;
            out[IOFF + (size_t)token * TOPK + lane] = (float)mye;
        }

        // flag risky tokens (min adjacent rel gap over top-9)
        float cv9 = fmaxf(v0, v1);
#pragma unroll
        for (int o = 16; o > 0; o >>= 1) cv9 = fmaxf(cv9, __shfl_xor_sync(0xFFFFFFFFu, cv9, o));
        float nxt = __shfl_down_sync(0xFFFFFFFFu, myv, 1);
        if (lane == TOPK - 1) nxt = cv9;
        bool risky = (lane < TOPK) && ((myv - nxt) < GAPTHRESH * myv);
        if (__any_sync(0xFFFFFFFFu, risky) && lane == 0) {
            int idx = atomicAdd(&g_nflag, 1);
            g_flagged[idx] = token;
        }
    }
}

// ---------------------------------------------------------------------------
// Fixup: bit-exact R1 arithmetic for flagged tokens (serial fp32 fmaf dot,
// k ascending + R1's fp32 router math). R1 passed all tokens.
// ---------------------------------------------------------------------------
__global__ __launch_bounds__(128, 1)
void fixup_kernel(const float* __restrict__ X,
                  const float* __restrict__ noise,
                  const float* __restrict__ b_route,
                  const float* __restrict__ b_noise,
                  const float* __restrict__ Wr,
                  const float* __restrict__ Wn,
                  float* __restrict__ out)
{
    __shared__ float sx[KDIM];
    __shared__ float slog[NCMB];
    const int tid = threadIdx.x;
    const int nf = g_nflag;

    for (int f = blockIdx.x; f < nf; f += gridDim.x) {
        const int token = g_flagged[f];

        for (int k = tid; k < KDIM; k += 128)
            sx[k] = X[(size_t)token * KDIM + k];
        __syncthreads();

        {
            const float* w = (tid < EEXP) ? (Wr + tid) : (Wn + (tid - EEXP));
            float acc = 0.0f;
#pragma unroll 8
            for (int k = 0; k < KDIM; k++)
                acc = fmaf(sx[k], w[(size_t)k * EEXP], acc);
            slog[tid] = acc;
        }
        __syncthreads();

        if (tid < 32) {
            const int lane = tid;
            const int e0 = lane, e1 = lane + 32;

            float lr0 = slog[e0] + b_route[e0];
            float lr1 = slog[e1] + b_route[e1];
            float ln0 = slog[EEXP + e0] + b_noise[e0];
            float ln1 = slog[EEXP + e1] + b_noise[e1];

            const float* nz = noise + (size_t)token * EEXP;
            float l0 = lr0 + nz[e0] * softplus_f(ln0);
            float l1 = lr1 + nz[e1] * softplus_f(ln1);

            float mx = fmaxf(l0, l1);
#pragma unroll
            for (int o = 16; o > 0; o >>= 1) mx = fmaxf(mx, __shfl_xor_sync(0xFFFFFFFFu, mx, o));
            float p0 = expf(l0 - mx);
            float p1 = expf(l1 - mx);
            float sum = p0 + p1;
#pragma unroll
            for (int o = 16; o > 0; o >>= 1) sum += __shfl_xor_sync(0xFFFFFFFFu, sum, o);
            p0 /= sum;
            p1 /= sum;

            out[POFF + (size_t)token * EEXP + e0] = p0;
            out[POFF + (size_t)token * EEXP + e1] = p1;

            float v0 = p0, v1 = p1;
            float myv = 0.0f;
            int   mye = 0;
            float tsum = 0.0f;

#pragma unroll
            for (int i = 0; i < TOPK; i++) {
                float cv; int ce;
                if (v1 > v0) { cv = v1; ce = e1; } else { cv = v0; ce = e0; }
#pragma unroll
                for (int o = 16; o > 0; o >>= 1) {
                    float ov = __shfl_xor_sync(0xFFFFFFFFu, cv, o);
                    int   oe = __shfl_xor_sync(0xFFFFFFFFu, ce, o);
                    if (ov > cv || (ov == cv && oe < ce)) { cv = ov; ce = oe; }
                }
                tsum += cv;
                if (lane == i) { myv = cv; mye = ce; }
                if (ce == e0) v0 = -1e30f;
                else if (ce == e1) v1 = -1e30f;
            }

            if (lane < TOPK) {
                out[WOFF + (size_t)token * TOPK + lane] = myv / tsum;
                out[IOFF + (size_t)token * TOPK + lane] = (float)mye;
            }
        }
        __syncthreads();
    }
}

// ---------------------------------------------------------------------------
extern "C" void kernel_launch(void* const* d_in, const int* in_sizes, int n_in,
                              void* d_out, int out_size)
{
    const float* x     = (const float*)d_in[0];
    const float* noise = (const float*)d_in[1];
    const float* Wr    = (const float*)d_in[2];
    const float* br    = (const float*)d_in[3];
    const float* Wn    = (const float*)d_in[4];
    const float* bn    = (const float*)d_in[5];
    float* out = (float*)d_out;

    cudaFuncSetAttribute(gemm_fused, cudaFuncAttributeMaxDynamicSharedMemorySize, SMEM_B);

    reset_flags<<<1, 32>>>();
    prep_interleave<<<(KDIM / 2) * NCMB / 256, 256>>>(Wr, Wn);
    gemm_fused<<<MTOT / BM, 256, SMEM_B>>>(x, noise, br, bn, out);
    fixup_kernel<<<128, 128>>>(x, noise, br, bn, Wr, Wn, out);
}

// round 16
// speedup vs baseline: 1.7162x; 1.7162x over previous
#include <cuda_runtime.h>
#include <cuda_fp16.h>
#include <math.h>
#include <cstdint>

// ---------------- problem constants ----------------
#define MTOT 16384
#define KDIM 4096
#define EEXP 64
#define NCMB 128
#define TOPK 8
#define WOFF 0
#define IOFF (MTOT * TOPK)
#define POFF (2 * MTOT * TOPK)

#define LOSCALE 2048.0f
#define LOINV   4.8828125e-4f   // 1/2048
#define GAPTHRESH 2.0e-4f       // relative adjacent-gap flag threshold

// ---------------- GEMM config (128x128, 1 wave, NO fold) ----------------
#define BM 128
#define BK 32
#define KITER (KDIM / BK)        // 128
#define NSTAGE 3
#define AST 40
#define BSTH 40
#define A_TILE_B (BM * AST * 4)      // 20480
#define B_TILE_B (NCMB * BSTH * 2)   // 10240
#define STAGE_B (A_TILE_B + 2 * B_TILE_B)   // 40960
#define SMEM_B (NSTAGE * STAGE_B)           // 122880

// scratch
__device__ float  g_logits[MTOT * NCMB];
__device__ __half g_W1[NCMB * KDIM];   // W^T hi        [n][k]
__device__ __half g_W2[NCMB * KDIM];   // W^T lo * 2048 [n][k]
__device__ int    g_nflag;
__device__ int    g_flagged[MTOT];

// ---------------- helpers ----------------
__device__ __forceinline__ uint32_t smem_u32(const void* p) {
    uint32_t a;
    asm("{ .reg .u64 t; cvta.to.shared.u64 t, %1; cvt.u32.u64 %0, t; }" : "=r"(a) : "l"(p));
    return a;
}
#define CP16(dst, src) asm volatile("cp.async.cg.shared.global [%0], [%1], 16;" :: "r"(dst), "l"(src) : "memory")
#define CP_COMMIT()    asm volatile("cp.async.commit_group;" ::: "memory")
#define CP_WAIT1()     asm volatile("cp.async.wait_group 1;" ::: "memory")
#define CP_WAIT0()     asm volatile("cp.async.wait_group 0;" ::: "memory")

#define LDSM4(r, addr) \
    asm volatile("ldmatrix.sync.aligned.m8n8.x4.shared.b16 {%0,%1,%2,%3}, [%4];" \
        : "=r"((r)[0]), "=r"((r)[1]), "=r"((r)[2]), "=r"((r)[3]) : "r"(addr))

#define MMA16816(d, a, b0, b1) \
    asm volatile("mma.sync.aligned.m16n8k16.row.col.f32.f16.f16.f32 " \
        "{%0,%1,%2,%3}, {%4,%5,%6,%7}, {%8,%9}, {%0,%1,%2,%3};" \
        : "+f"((d)[0]), "+f"((d)[1]), "+f"((d)[2]), "+f"((d)[3]) \
        : "r"((a)[0]), "r"((a)[1]), "r"((a)[2]), "r"((a)[3]), "r"(b0), "r"(b1))

__device__ __forceinline__ uint32_t h2u(__half2 h) { return *reinterpret_cast<uint32_t*>(&h); }

__device__ __forceinline__ void split_pair(float2 v, uint32_t& hi, uint32_t& lo) {
    __half2 h = __floats2half2_rn(v.x, v.y);
    float2  c = __half22float2(h);
    __half2 l = __floats2half2_rn((v.x - c.x) * LOSCALE, (v.y - c.y) * LOSCALE);
    hi = h2u(h);
    lo = h2u(l);
}

__device__ __forceinline__ float softplus_f(float z) {
    return fmaxf(z, 0.0f) + log1pf(expf(-fabsf(z)));
}

// ---------------------------------------------------------------------------
__global__ void reset_flags() { if (threadIdx.x == 0) g_nflag = 0; }

// ---------------------------------------------------------------------------
// Prep: transpose + scaled fp16-split [W_route | W_noise] -> g_W1/g_W2
// ---------------------------------------------------------------------------
__global__ void prep_splitW(const float* __restrict__ Wr, const float* __restrict__ Wn) {
    __shared__ float t[32][33];
    const int kx = blockIdx.x * 32, ny = blockIdx.y * 32;
    const int tx = threadIdx.x, ty = threadIdx.y;  // 32 x 8
#pragma unroll
    for (int r = 0; r < 4; r++) {
        int k = kx + ty + r * 8, n = ny + tx;
        float v = (n < EEXP) ? Wr[(size_t)k * EEXP + n] : Wn[(size_t)k * EEXP + (n - EEXP)];
        t[ty + r * 8][tx] = v;
    }
    __syncthreads();
#pragma unroll
    for (int r = 0; r < 4; r++) {
        int n = ny + ty + r * 8, k = kx + tx;
        float v = t[tx][ty + r * 8];
        __half h1 = __float2half_rn(v);
        __half h2 = __float2half_rn((v - __half2float(h1)) * LOSCALE);
        g_W1[(size_t)n * KDIM + k] = h1;
        g_W2[(size_t)n * KDIM + k] = h2;
    }
}

// ---------------------------------------------------------------------------
// GEMM (R12, verbatim): fp16 scaled-split, 3 products, 2 fp32 accumulators
// CTA: 128m x 128n x 32k, 8 warps (4m x 2n)
// ---------------------------------------------------------------------------
__global__ __launch_bounds__(256, 1)
void gemm_mma(const float* __restrict__ X)
{
    extern __shared__ char smem[];
    const uint32_t sb = smem_u32(smem);
    const int tid = threadIdx.x;
    const int wid = tid >> 5, lane = tid & 31;
    const int warpM = wid & 3, warpN = wid >> 2;
    const int m0 = blockIdx.x * BM;

    const int cm   = tid >> 1;
    const int chal = tid & 1;
    const float* aSrc = X + (size_t)(m0 + cm) * KDIM + chal * 16;
    const char*  b1Src = reinterpret_cast<const char*>(g_W1) + (size_t)cm * (KDIM * 2) + chal * 32;
    const char*  b2Src = reinterpret_cast<const char*>(g_W2) + (size_t)cm * (KDIM * 2) + chal * 32;
    const uint32_t aDstBase  = sb + cm * (AST * 4) + chal * 64;
    const uint32_t b1DstBase = sb + A_TILE_B + cm * (BSTH * 2) + chal * 32;
    const uint32_t b2DstBase = sb + A_TILE_B + B_TILE_B + cm * (BSTH * 2) + chal * 32;

    auto issue_stage = [&](int kt) {
        const uint32_t so = (kt % NSTAGE) * STAGE_B;
        const float* as = aSrc + kt * BK;
#pragma unroll
        for (int j = 0; j < 4; j++) CP16(so + aDstBase + j * 16, as + j * 4);
        const char* b1s = b1Src + kt * (BK * 2);
        const char* b2s = b2Src + kt * (BK * 2);
#pragma unroll
        for (int j = 0; j < 2; j++) CP16(so + b1DstBase + j * 16, b1s + j * 16);
#pragma unroll
        for (int j = 0; j < 2; j++) CP16(so + b2DstBase + j * 16, b2s + j * 16);
        CP_COMMIT();
    };

    issue_stage(0);
    issue_stage(1);

    const int r0 = lane >> 2;
    const int c0 = (lane & 3) * 2;
    const int aRow = warpM * 32 + r0;
    const int tg = lane >> 3, tr = lane & 7;
    const uint32_t bLaneOff = (uint32_t)(warpN * 64 + (tg >> 1) * 8 + tr) * (BSTH * 2) + (tg & 1) * 16;

    float accH[2][8][4];
    float accL[2][8][4];
#pragma unroll
    for (int a = 0; a < 2; a++)
#pragma unroll
        for (int b = 0; b < 8; b++)
#pragma unroll
            for (int c = 0; c < 4; c++) { accH[a][b][c] = 0.0f; accL[a][b][c] = 0.0f; }

    for (int i = 0; i < KITER; ++i) {
        if (i == KITER - 1) { CP_WAIT0(); } else { CP_WAIT1(); }
        __syncthreads();

        if (i + 2 < KITER) issue_stage(i + 2);

        const uint32_t so = (i % NSTAGE) * STAGE_B;
        const float* sA = reinterpret_cast<const float*>(smem + so);
        const uint32_t b1B = sb + so + A_TILE_B;
        const uint32_t b2B = sb + so + A_TILE_B + B_TILE_B;

#pragma unroll
        for (int ks = 0; ks < 2; ks++) {
            const int kbase = ks * 16 + c0;
            uint32_t ah[2][4], al[2][4];
#pragma unroll
            for (int mt = 0; mt < 2; mt++) {
                const int mr = aRow + mt * 16;
                float2 p0 = *reinterpret_cast<const float2*>(&sA[(mr    ) * AST + kbase    ]);
                float2 p1 = *reinterpret_cast<const float2*>(&sA[(mr + 8) * AST + kbase    ]);
                float2 p2 = *reinterpret_cast<const float2*>(&sA[(mr    ) * AST + kbase + 8]);
                float2 p3 = *reinterpret_cast<const float2*>(&sA[(mr + 8) * AST + kbase + 8]);
                split_pair(p0, ah[mt][0], al[mt][0]);
                split_pair(p1, ah[mt][1], al[mt][1]);
                split_pair(p2, ah[mt][2], al[mt][2]);
                split_pair(p3, ah[mt][3], al[mt][3]);
            }
#pragma unroll
            for (int g = 0; g < 4; g++) {
                uint32_t bh[4], bl[4];
                const uint32_t go = bLaneOff + g * (16 * BSTH * 2) + ks * 32;
                LDSM4(bh, b1B + go);
                LDSM4(bl, b2B + go);
#pragma unroll
                for (int mt = 0; mt < 2; mt++) {
                    MMA16816(accH[mt][2 * g],     ah[mt], bh[0], bh[1]);
                    MMA16816(accL[mt][2 * g],     ah[mt], bl[0], bl[1]);
                    MMA16816(accL[mt][2 * g],     al[mt], bh[0], bh[1]);
                    MMA16816(accH[mt][2 * g + 1], ah[mt], bh[2], bh[3]);
                    MMA16816(accL[mt][2 * g + 1], ah[mt], bl[2], bl[3]);
                    MMA16816(accL[mt][2 * g + 1], al[mt], bh[2], bh[3]);
                }
            }
        }
    }

#pragma unroll
    for (int mt = 0; mt < 2; mt++) {
#pragma unroll
        for (int j = 0; j < 8; j++) {
            const int row = m0 + warpM * 32 + mt * 16 + r0;
            const int col = warpN * 64 + j * 8 + c0;
            float2 v0, v1;
            v0.x = fmaf(accL[mt][j][0], LOINV, accH[mt][j][0]);
            v0.y = fmaf(accL[mt][j][1], LOINV, accH[mt][j][1]);
            v1.x = fmaf(accL[mt][j][2], LOINV, accH[mt][j][2]);
            v1.y = fmaf(accL[mt][j][3], LOINV, accH[mt][j][3]);
            *reinterpret_cast<float2*>(&g_logits[(size_t)row * NCMB + col]) = v0;
            *reinterpret_cast<float2*>(&g_logits[(size_t)(row + 8) * NCMB + col]) = v1;
        }
    }
}

// ---------------------------------------------------------------------------
// Router (fp32) + risky-token flagging (min adjacent rel gap in top-9)
// ---------------------------------------------------------------------------
__global__ __launch_bounds__(256, 8)
void router_kernel(const float* __restrict__ noise,
                   const float* __restrict__ b_route,
                   const float* __restrict__ b_noise,
                   float* __restrict__ out)
{
    const int lane = threadIdx.x & 31;
    const int wrp  = threadIdx.x >> 5;
    const int token = blockIdx.x * 8 + wrp;

    const float* rowp = g_logits + (size_t)token * NCMB;
    const int e0 = lane, e1 = lane + 32;

    float lr0 = rowp[e0] + b_route[e0];
    float lr1 = rowp[e1] + b_route[e1];
    float ln0 = rowp[EEXP + e0] + b_noise[e0];
    float ln1 = rowp[EEXP + e1] + b_noise[e1];

    const float* nz = noise + (size_t)token * EEXP;
    float l0 = lr0 + nz[e0] * softplus_f(ln0);
    float l1 = lr1 + nz[e1] * softplus_f(ln1);

    float mx = fmaxf(l0, l1);
#pragma unroll
    for (int o = 16; o > 0; o >>= 1) mx = fmaxf(mx, __shfl_xor_sync(0xFFFFFFFFu, mx, o));
    float p0 = expf(l0 - mx);
    float p1 = expf(l1 - mx);
    float sum = p0 + p1;
#pragma unroll
    for (int o = 16; o > 0; o >>= 1) sum += __shfl_xor_sync(0xFFFFFFFFu, sum, o);
    p0 /= sum;
    p1 /= sum;

    out[POFF + (size_t)token * EEXP + e0] = p0;
    out[POFF + (size_t)token * EEXP + e1] = p1;

    float v0 = p0, v1 = p1;
    float myv = 0.0f;
    int   mye = 0;
    float tsum = 0.0f;

#pragma unroll
    for (int i = 0; i < TOPK; i++) {
        float cv; int ce;
        if (v1 > v0) { cv = v1; ce = e1; } else { cv = v0; ce = e0; }
#pragma unroll
        for (int o = 16; o > 0; o >>= 1) {
            float ov = __shfl_xor_sync(0xFFFFFFFFu, cv, o);
            int   oe = __shfl_xor_sync(0xFFFFFFFFu, ce, o);
            if (ov > cv || (ov == cv && oe < ce)) { cv = ov; ce = oe; }
        }
        tsum += cv;
        if (lane == i) { myv = cv; mye = ce; }
        if (ce == e0) v0 = -1e30f;
        else if (ce == e1) v1 = -1e30f;
    }

    if (lane < TOPK) {
        out[WOFF + (size_t)token * TOPK + lane] = myv / tsum;
        out[IOFF + (size_t)token * TOPK + lane] = (float)mye;
    }

    // flag risky tokens: 9th max, then min adjacent relative gap over top-9
    float cv9 = fmaxf(v0, v1);
#pragma unroll
    for (int o = 16; o > 0; o >>= 1) cv9 = fmaxf(cv9, __shfl_xor_sync(0xFFFFFFFFu, cv9, o));
    float nxt = __shfl_down_sync(0xFFFFFFFFu, myv, 1);
    if (lane == TOPK - 1) nxt = cv9;
    bool risky = (lane < TOPK) && ((myv - nxt) < GAPTHRESH * myv);
    if (__any_sync(0xFFFFFFFFu, risky) && lane == 0) {
        int idx = atomicAdd(&g_nflag, 1);
        g_flagged[idx] = token;
    }
}

// ---------------------------------------------------------------------------
// Fixup (PARALLELIZED): one token per block, grid = MTOT/4 blocks; blocks
// with blockIdx.x >= nflag exit immediately. ~13 CTAs/SM resident ->
// ~1900 latency-bound chains in flight instead of 128.
// Per-token arithmetic identical to R12 (serial fp32 fmaf, k ascending).
// ---------------------------------------------------------------------------
__global__ __launch_bounds__(128, 8)
void fixup_kernel(const float* __restrict__ X,
                  const float* __restrict__ noise,
                  const float* __restrict__ b_route,
                  const float* __restrict__ b_noise,
                  const float* __restrict__ Wr,
                  const float* __restrict__ Wn,
                  float* __restrict__ out)
{
    __shared__ float sx[KDIM];
    __shared__ float slog[NCMB];
    const int tid = threadIdx.x;

    const int f = blockIdx.x;
    if (f >= g_nflag) return;
    const int token = g_flagged[f];

    for (int k = tid; k < KDIM; k += 128)
        sx[k] = X[(size_t)token * KDIM + k];
    __syncthreads();

    {
        const float* w = (tid < EEXP) ? (Wr + tid) : (Wn + (tid - EEXP));
        float acc = 0.0f;
#pragma unroll 8
        for (int k = 0; k < KDIM; k++)
            acc = fmaf(sx[k], w[(size_t)k * EEXP], acc);
        slog[tid] = acc;
    }
    __syncthreads();

    if (tid < 32) {
        const int lane = tid;
        const int e0 = lane, e1 = lane + 32;

        float lr0 = slog[e0] + b_route[e0];
        float lr1 = slog[e1] + b_route[e1];
        float ln0 = slog[EEXP + e0] + b_noise[e0];
        float ln1 = slog[EEXP + e1] + b_noise[e1];

        const float* nz = noise + (size_t)token * EEXP;
        float l0 = lr0 + nz[e0] * softplus_f(ln0);
        float l1 = lr1 + nz[e1] * softplus_f(ln1);

        float mx = fmaxf(l0, l1);
#pragma unroll
        for (int o = 16; o > 0; o >>= 1) mx = fmaxf(mx, __shfl_xor_sync(0xFFFFFFFFu, mx, o));
        float p0 = expf(l0 - mx);
        float p1 = expf(l1 - mx);
        float sum = p0 + p1;
#pragma unroll
        for (int o = 16; o > 0; o >>= 1) sum += __shfl_xor_sync(0xFFFFFFFFu, sum, o);
        p0 /= sum;
        p1 /= sum;

        out[POFF + (size_t)token * EEXP + e0] = p0;
        out[POFF + (size_t)token * EEXP + e1] = p1;

        float v0 = p0, v1 = p1;
        float myv = 0.0f;
        int   mye = 0;
        float tsum = 0.0f;

#pragma unroll
        for (int i = 0; i < TOPK; i++) {
            float cv; int ce;
            if (v1 > v0) { cv = v1; ce = e1; } else { cv = v0; ce = e0; }
#pragma unroll
            for (int o = 16; o > 0; o >>= 1) {
                float ov = __shfl_xor_sync(0xFFFFFFFFu, cv, o);
                int   oe = __shfl_xor_sync(0xFFFFFFFFu, ce, o);
                if (ov > cv || (ov == cv && oe < ce)) { cv = ov; ce = oe; }
            }
            tsum += cv;
            if (lane == i) { myv = cv; mye = ce; }
            if (ce == e0) v0 = -1e30f;
            else if (ce == e1) v1 = -1e30f;
        }

        if (lane < TOPK) {
            out[WOFF + (size_t)token * TOPK + lane] = myv / tsum;
            out[IOFF + (size_t)token * TOPK + lane] = (float)mye;
        }
    }
}

// ---------------------------------------------------------------------------
extern "C" void kernel_launch(void* const* d_in, const int* in_sizes, int n_in,
                              void* d_out, int out_size)
{
    const float* x     = (const float*)d_in[0];
    const float* noise = (const float*)d_in[1];
    const float* Wr    = (const float*)d_in[2];
    const float* br    = (const float*)d_in[3];
    const float* Wn    = (const float*)d_in[4];
    const float* bn    = (const float*)d_in[5];
    float* out = (float*)d_out;

    cudaFuncSetAttribute(gemm_mma, cudaFuncAttributeMaxDynamicSharedMemorySize, SMEM_B);

    reset_flags<<<1, 32>>>();
    prep_splitW<<<dim3(KDIM / 32, NCMB / 32), dim3(32, 8)>>>(Wr, Wn);
    gemm_mma<<<MTOT / BM, 256, SMEM_B>>>(x);
    router_kernel<<<MTOT / 8, 256>>>(noise, br, bn, out);
    // one token per block; blocks beyond g_nflag exit immediately
    fixup_kernel<<<MTOT / 4, 128>>>(x, noise, br, bn, Wr, Wn, out);
}